// round 6
// baseline (speedup 1.0000x reference)
#include <cuda_runtime.h>
#include <cstdint>

// ---------------------------------------------------------------------------
// 2-layer GCN, pull-based (atomic-free feature aggregation):
//   H1' = (x @ W1) * dis          (per-row scale in GEMM epilogue)
//   agg1[d] = dis[d]*(sum_{s in N(d)} H1'[s] + H1'[d]) + b1
//   H2' = (relu(agg1) @ W2) * dis
//   out[d]  = dis[d]*(sum_{s in N(d)} H2'[s] + H2'[d]) + b2
// CSR of incoming edges rebuilt each launch with int atomics only.
// Edge dtype (int32 vs int64) detected at runtime — JAX without x64 silently
// emits int32 even when the reference asks for int64.
// ---------------------------------------------------------------------------

#define N_NODES 50000
#define E_MAX   800000
#define D_HID   128

// Scratch (allocation-free __device__ globals, ~81 MB total)
__device__ int   g_is64;
__device__ int   g_cnt   [N_NODES];
__device__ int   g_rowptr[N_NODES + 1];
__device__ int   g_cursor[N_NODES];
__device__ int   g_col   [E_MAX];
__device__ float g_dis   [N_NODES];
__device__ float g_h     [(size_t)N_NODES * D_HID];
__device__ float g_agg   [(size_t)N_NODES * D_HID];
__device__ float g_h2    [(size_t)N_NODES * D_HID];

__device__ __forceinline__ int edge_at(const void* EI, long long idx, int is64) {
    if (is64) return (int)(((const long long*)EI)[idx]);
    return ((const int*)EI)[idx];
}

// ---------------------------------------------------------------------------
// Edge dtype detection: genuine int64 data has every value in [0, N).
// int32 data reinterpreted as int64 packs two random ints per word ->
// value >= 2^32 (or negative) with prob ~1 per element. 64 samples checked
// across both halves of edge_index -> misdetection prob ~ (2e-5)^64 ~ 0.
// ---------------------------------------------------------------------------
__global__ void detect_kernel(const void* EI, int E) {
    int lane = threadIdx.x;
    const long long* p = (const long long*)EI;
    bool ok = true;
    {   // 32 samples from the src half
        long long v = p[lane];
        if (v < 0 || v >= N_NODES) ok = false;
    }
    {   // 32 samples from the dst half (if int64, dst starts at E)
        long long v = p[E + lane];
        if (v < 0 || v >= N_NODES) ok = false;
    }
    unsigned m = __ballot_sync(0xffffffffu, ok);
    if (lane == 0) g_is64 = (m == 0xffffffffu) ? 1 : 0;
}

// ---------------------------------------------------------------------------
// CSR build
// ---------------------------------------------------------------------------
__global__ void zero_cnt_kernel(int* cnt, int n) {
    int i = blockIdx.x * blockDim.x + threadIdx.x;
    if (i < n) cnt[i] = 0;
}

__global__ void hist_kernel(const void* __restrict__ EI, int* cnt, int E) {
    int e = blockIdx.x * blockDim.x + threadIdx.x;
    if (e < E) {
        int d = edge_at(EI, (long long)E + e, g_is64);
        atomicAdd(&cnt[d], 1);
    }
}

// Single-block scan: rowptr/cursor = exclusive prefix of cnt; dis = rsqrt(1+cnt)
__global__ void scan_kernel(const int* __restrict__ cnt,
                            int* rowptr, int* cursor, float* dis, int n) {
    __shared__ int sums[1024];
    const int tid   = threadIdx.x;
    const int chunk = (n + 1023) / 1024;
    const int start = min(tid * chunk, n);
    const int end   = min(start + chunk, n);

    int s = 0;
    for (int i = start; i < end; i++) s += cnt[i];
    sums[tid] = s;
    __syncthreads();
    // Hillis-Steele inclusive scan
    for (int off = 1; off < 1024; off <<= 1) {
        int v = (tid >= off) ? sums[tid - off] : 0;
        __syncthreads();
        sums[tid] += v;
        __syncthreads();
    }
    int run = (tid == 0) ? 0 : sums[tid - 1];
    for (int i = start; i < end; i++) {
        rowptr[i] = run;
        cursor[i] = run;
        dis[i]    = rsqrtf(1.0f + (float)cnt[i]);
        run += cnt[i];
    }
    if (tid == 1023) rowptr[n] = sums[1023];  // total == E
}

__global__ void fill_kernel(const void* __restrict__ EI,
                            int* cursor, int* col, int E) {
    int e = blockIdx.x * blockDim.x + threadIdx.x;
    if (e < E) {
        int is64 = g_is64;
        int s = edge_at(EI, e, is64);
        int d = edge_at(EI, (long long)E + e, is64);
        int pos = atomicAdd(&cursor[d], 1);
        col[pos] = s;
    }
}

// ---------------------------------------------------------------------------
// Fused SGEMM:  H = act(X) @ W, epilogue scales by dis[row]:  H'[r] = h[r]*dis[r]
// BM=128, BN=128 (full output width), BK=16, 256 threads, 8x8 micro-tile.
// ---------------------------------------------------------------------------
#define BM 128
#define BN 128
#define BK 16
#define TM 8
#define TN 8

template <bool RELU>
__global__ __launch_bounds__(256, 2)
void gemm_scaled_kernel(const float* __restrict__ X,
                        const float* __restrict__ W,
                        const float* __restrict__ dis,
                        float* __restrict__ H,
                        int M, int K) {
    __shared__ __align__(16) float As[BK][BM];   // As[k][m]
    __shared__ __align__(16) float Bs[BK][BN];   // Bs[k][n]

    const int tid       = threadIdx.x;
    const int block_row = blockIdx.x * BM;
    const int trow      = (tid >> 4) * TM;
    const int tcol      = (tid & 15) * TN;

    float acc[TM][TN];
    #pragma unroll
    for (int i = 0; i < TM; i++)
        #pragma unroll
        for (int j = 0; j < TN; j++) acc[i][j] = 0.0f;

    for (int k0 = 0; k0 < K; k0 += BK) {
        #pragma unroll
        for (int it = 0; it < 2; it++) {
            int s    = tid + it * 256;     // 0..511 -> 128 rows x 4 quads
            int r    = s >> 2;
            int cq   = s & 3;
            int grow = block_row + r;
            float4 v = make_float4(0.f, 0.f, 0.f, 0.f);
            if (grow < M)
                v = *reinterpret_cast<const float4*>(X + (size_t)grow * K + k0 + cq * 4);
            if (RELU) {
                v.x = fmaxf(v.x, 0.f); v.y = fmaxf(v.y, 0.f);
                v.z = fmaxf(v.z, 0.f); v.w = fmaxf(v.w, 0.f);
            }
            As[cq * 4 + 0][r] = v.x;
            As[cq * 4 + 1][r] = v.y;
            As[cq * 4 + 2][r] = v.z;
            As[cq * 4 + 3][r] = v.w;
        }
        #pragma unroll
        for (int it = 0; it < 2; it++) {
            int s  = tid + it * 256;       // 16 rows x 32 quads
            int r  = s >> 5;
            int cq = s & 31;
            float4 v = *reinterpret_cast<const float4*>(W + (size_t)(k0 + r) * BN + cq * 4);
            *reinterpret_cast<float4*>(&Bs[r][cq * 4]) = v;
        }
        __syncthreads();

        #pragma unroll
        for (int k = 0; k < BK; k++) {
            float ra[TM], rb[TN];
            *reinterpret_cast<float4*>(&ra[0]) = *reinterpret_cast<const float4*>(&As[k][trow]);
            *reinterpret_cast<float4*>(&ra[4]) = *reinterpret_cast<const float4*>(&As[k][trow + 4]);
            *reinterpret_cast<float4*>(&rb[0]) = *reinterpret_cast<const float4*>(&Bs[k][tcol]);
            *reinterpret_cast<float4*>(&rb[4]) = *reinterpret_cast<const float4*>(&Bs[k][tcol + 4]);
            #pragma unroll
            for (int i = 0; i < TM; i++)
                #pragma unroll
                for (int j = 0; j < TN; j++)
                    acc[i][j] = fmaf(ra[i], rb[j], acc[i][j]);
        }
        __syncthreads();
    }

    #pragma unroll
    for (int i = 0; i < TM; i++) {
        int grow = block_row + trow + i;
        if (grow >= M) break;
        float d = dis[grow];
        #pragma unroll
        for (int j = 0; j < TN; j += 4) {
            float4 hv = make_float4(acc[i][j] * d, acc[i][j + 1] * d,
                                    acc[i][j + 2] * d, acc[i][j + 3] * d);
            *reinterpret_cast<float4*>(H + (size_t)grow * D_HID + tcol + j) = hv;
        }
    }
}

// ---------------------------------------------------------------------------
// Gather:  out[d] = dis[d]*( H'[d] + sum_{s in CSR[d]} H'[s] ) + bias
// One warp per node; lane l owns float4 at column 4l. 4-deep neighbor unroll.
// ---------------------------------------------------------------------------
__global__ __launch_bounds__(256)
void gather_kernel(const int* __restrict__ rowptr,
                   const int* __restrict__ col,
                   const float* __restrict__ dis,
                   const float* __restrict__ Hs,
                   const float* __restrict__ bias,
                   float* __restrict__ out, int n) {
    int w    = (blockIdx.x * blockDim.x + threadIdx.x) >> 5;
    int lane = threadIdx.x & 31;
    if (w >= n) return;

    const int beg = rowptr[w];
    const int end = rowptr[w + 1];
    const float* Hc = Hs + (size_t)lane * 4;   // lane-fixed column base

    float4 acc = *reinterpret_cast<const float4*>(Hc + (size_t)w * D_HID); // self

    int i = beg;
    for (; i + 4 <= end; i += 4) {
        int s0 = col[i], s1 = col[i + 1], s2 = col[i + 2], s3 = col[i + 3];
        float4 v0 = *reinterpret_cast<const float4*>(Hc + (size_t)s0 * D_HID);
        float4 v1 = *reinterpret_cast<const float4*>(Hc + (size_t)s1 * D_HID);
        float4 v2 = *reinterpret_cast<const float4*>(Hc + (size_t)s2 * D_HID);
        float4 v3 = *reinterpret_cast<const float4*>(Hc + (size_t)s3 * D_HID);
        acc.x += v0.x + v1.x + v2.x + v3.x;
        acc.y += v0.y + v1.y + v2.y + v3.y;
        acc.z += v0.z + v1.z + v2.z + v3.z;
        acc.w += v0.w + v1.w + v2.w + v3.w;
    }
    for (; i < end; i++) {
        int s = col[i];
        float4 v = *reinterpret_cast<const float4*>(Hc + (size_t)s * D_HID);
        acc.x += v.x; acc.y += v.y; acc.z += v.z; acc.w += v.w;
    }

    float dd  = dis[w];
    float4 bv = *reinterpret_cast<const float4*>(bias + (size_t)lane * 4);
    float4 o  = make_float4(fmaf(acc.x, dd, bv.x), fmaf(acc.y, dd, bv.y),
                            fmaf(acc.z, dd, bv.z), fmaf(acc.w, dd, bv.w));
    *reinterpret_cast<float4*>(out + (size_t)w * D_HID + (size_t)lane * 4) = o;
}

// ---------------------------------------------------------------------------
// Launch
// ---------------------------------------------------------------------------
static inline int cdiv(long long a, long long b) { return (int)((a + b - 1) / b); }

extern "C" void kernel_launch(void* const* d_in, const int* in_sizes, int n_in,
                              void* d_out, int out_size) {
    const float* X   = (const float*)d_in[0];   // [N, 256]
    const void*  EI  = d_in[1];                 // [2, E], int32 or int64
    const float* W1  = (const float*)d_in[2];   // [256, 128]
    const float* b1  = (const float*)d_in[3];   // [128]
    const float* W2  = (const float*)d_in[4];   // [128, 128]
    const float* b2  = (const float*)d_in[5];   // [128]
    float*       OUT = (float*)d_out;           // [N, 128]

    const int M  = in_sizes[0] / 256;    // 50000
    const int E  = in_sizes[1] / 2;      // 800000
    const int K1 = in_sizes[2] / D_HID;  // 256

    int *p_cnt, *p_rowptr, *p_cursor, *p_col;
    float *p_dis, *p_h, *p_agg, *p_h2;
    cudaGetSymbolAddress((void**)&p_cnt,    g_cnt);
    cudaGetSymbolAddress((void**)&p_rowptr, g_rowptr);
    cudaGetSymbolAddress((void**)&p_cursor, g_cursor);
    cudaGetSymbolAddress((void**)&p_col,    g_col);
    cudaGetSymbolAddress((void**)&p_dis,    g_dis);
    cudaGetSymbolAddress((void**)&p_h,      g_h);
    cudaGetSymbolAddress((void**)&p_agg,    g_agg);
    cudaGetSymbolAddress((void**)&p_h2,     g_h2);

    // --- edge dtype detection + CSR of incoming edges (int atomics only) ---
    detect_kernel  <<<1, 32>>>(EI, E);
    zero_cnt_kernel<<<cdiv(M, 256), 256>>>(p_cnt, M);
    hist_kernel    <<<cdiv(E, 256), 256>>>(EI, p_cnt, E);
    scan_kernel    <<<1, 1024>>>(p_cnt, p_rowptr, p_cursor, p_dis, M);
    fill_kernel    <<<cdiv(E, 256), 256>>>(EI, p_cursor, p_col, E);

    const int gemm_blocks   = cdiv(M, BM);
    const int gather_blocks = cdiv(M, 8);   // 8 warps per 256-thread block

    // --- layer 1 ---
    gemm_scaled_kernel<false><<<gemm_blocks, 256>>>(X, W1, p_dis, p_h, M, K1);
    gather_kernel<<<gather_blocks, 256>>>(p_rowptr, p_col, p_dis, p_h, b1, p_agg, M);

    // --- layer 2 ---
    gemm_scaled_kernel<true><<<gemm_blocks, 256>>>(p_agg, W2, p_dis, p_h2, M, D_HID);
    gather_kernel<<<gather_blocks, 256>>>(p_rowptr, p_col, p_dis, p_h2, b2, OUT, M);
}

// round 7
// speedup vs baseline: 1.6163x; 1.6163x over previous
#include <cuda_runtime.h>
#include <cstdint>

// ---------------------------------------------------------------------------
// 2-layer GCN, pull-based (atomic-free feature aggregation):
//   H1' = (x @ W1) * dis ; agg1[d] = dis[d]*(sum_N H1' + H1'[d]) + b1
//   H2' = (relu(agg1) @ W2) * dis ; out likewise with b2
// CSR rebuilt per launch (int atomics + 3-phase multi-block scan).
// GEMM inner loop uses packed fma.rn.f32x2 (FFMA2, sm_100+).
// ---------------------------------------------------------------------------

#define N_NODES 50000
#define E_MAX   800000
#define D_HID   128

typedef unsigned long long u64;

// Scratch (allocation-free __device__ globals)
__device__ int   g_is64;
__device__ int   g_cnt     [N_NODES];
__device__ int   g_rowptr  [N_NODES + 1];
__device__ int   g_cursor  [N_NODES];
__device__ int   g_col     [E_MAX];
__device__ int   g_blocksum[256];
__device__ int   g_blockoff[256];
__device__ float g_dis     [N_NODES];
__device__ float g_h       [(size_t)N_NODES * D_HID];
__device__ float g_agg     [(size_t)N_NODES * D_HID];
__device__ float g_h2      [(size_t)N_NODES * D_HID];

__device__ __forceinline__ int edge_at(const void* EI, long long idx, int is64) {
    if (is64) return (int)(((const long long*)EI)[idx]);
    return ((const int*)EI)[idx];
}

// ---------------------------------------------------------------------------
// Edge dtype detection (JAX w/o x64 silently emits int32 for "int64")
// ---------------------------------------------------------------------------
__global__ void detect_kernel(const void* EI, int E) {
    int lane = threadIdx.x;
    const long long* p = (const long long*)EI;
    bool ok = true;
    { long long v = p[lane];        if (v < 0 || v >= N_NODES) ok = false; }
    { long long v = p[E + lane];    if (v < 0 || v >= N_NODES) ok = false; }
    unsigned m = __ballot_sync(0xffffffffu, ok);
    if (lane == 0) g_is64 = (m == 0xffffffffu) ? 1 : 0;
}

// ---------------------------------------------------------------------------
// CSR build
// ---------------------------------------------------------------------------
__global__ void zero_cnt_kernel(int* cnt, int n) {
    int i = blockIdx.x * blockDim.x + threadIdx.x;
    if (i < n) cnt[i] = 0;
}

__global__ void hist_kernel(const void* __restrict__ EI, int* cnt, int E) {
    int e = blockIdx.x * blockDim.x + threadIdx.x;
    if (e < E) {
        int d = edge_at(EI, (long long)E + e, g_is64);
        atomicAdd(&cnt[d], 1);
    }
}

// --- 3-phase scan: A) per-block reduce  B) scan block sums  C) write ---
__global__ void scanA_kernel(const int* __restrict__ cnt, int n) {
    __shared__ int sm[256];
    int i = blockIdx.x * 256 + threadIdx.x;
    sm[threadIdx.x] = (i < n) ? cnt[i] : 0;
    __syncthreads();
    #pragma unroll
    for (int off = 128; off > 0; off >>= 1) {
        if (threadIdx.x < off) sm[threadIdx.x] += sm[threadIdx.x + off];
        __syncthreads();
    }
    if (threadIdx.x == 0) g_blocksum[blockIdx.x] = sm[0];
}

__global__ void scanB_kernel(int nb) {
    __shared__ int sm[256];
    int t = threadIdx.x;
    int v = (t < nb) ? g_blocksum[t] : 0;
    sm[t] = v;
    __syncthreads();
    #pragma unroll
    for (int off = 1; off < 256; off <<= 1) {
        int u = (t >= off) ? sm[t - off] : 0;
        __syncthreads();
        sm[t] += u;
        __syncthreads();
    }
    g_blockoff[t] = sm[t] - v;   // exclusive prefix
}

__global__ void scanC_kernel(const int* __restrict__ cnt,
                             int* rowptr, int* cursor, float* dis, int n) {
    __shared__ int sm[256];
    int t = threadIdx.x;
    int i = blockIdx.x * 256 + t;
    int v = (i < n) ? cnt[i] : 0;
    sm[t] = v;
    __syncthreads();
    #pragma unroll
    for (int off = 1; off < 256; off <<= 1) {
        int u = (t >= off) ? sm[t - off] : 0;
        __syncthreads();
        sm[t] += u;
        __syncthreads();
    }
    if (i < n) {
        int excl = g_blockoff[blockIdx.x] + sm[t] - v;
        rowptr[i] = excl;
        cursor[i] = excl;
        dis[i]    = rsqrtf(1.0f + (float)v);
        if (i == n - 1) rowptr[n] = excl + v;   // total == E
    }
}

__global__ void fill_kernel(const void* __restrict__ EI,
                            int* cursor, int* col, int E) {
    int e = blockIdx.x * blockDim.x + threadIdx.x;
    if (e < E) {
        int is64 = g_is64;
        int s = edge_at(EI, e, is64);
        int d = edge_at(EI, (long long)E + e, is64);
        int pos = atomicAdd(&cursor[d], 1);
        col[pos] = s;
    }
}

// ---------------------------------------------------------------------------
// Fused SGEMM with packed f32x2 FMA:  H = act(X) @ W, epilogue *= dis[row]
// BM=128, BN=128, BK=16, 256 threads, 8x8 micro-tile (stored as 8x4 f32x2).
// ---------------------------------------------------------------------------
#define BM 128
#define BN 128
#define BK 16
#define TM 8
#define TN 8

#define FMA2(acc, a2, b2) \
    asm("fma.rn.f32x2 %0, %1, %2, %0;" : "+l"(acc) : "l"(a2), "l"(b2))
#define DUP2(dst, x) \
    asm("mov.b64 %0, {%1, %1};" : "=l"(dst) : "r"(x))

template <bool RELU>
__global__ __launch_bounds__(256, 2)
void gemm_scaled_kernel(const float* __restrict__ X,
                        const float* __restrict__ W,
                        const float* __restrict__ dis,
                        float* __restrict__ H,
                        int M, int K) {
    __shared__ __align__(16) float As[BK][BM];   // As[k][m]
    __shared__ __align__(16) float Bs[BK][BN];   // Bs[k][n]

    const int tid       = threadIdx.x;
    const int block_row = blockIdx.x * BM;
    const int trow      = (tid >> 4) * TM;
    const int tcol      = (tid & 15) * TN;

    u64 acc2[TM][TN / 2];
    #pragma unroll
    for (int i = 0; i < TM; i++)
        #pragma unroll
        for (int j = 0; j < TN / 2; j++) acc2[i][j] = 0ull;

    for (int k0 = 0; k0 < K; k0 += BK) {
        #pragma unroll
        for (int it = 0; it < 2; it++) {
            int s    = tid + it * 256;     // 0..511 -> 128 rows x 4 quads
            int r    = s >> 2;
            int cq   = s & 3;
            int grow = block_row + r;
            float4 v = make_float4(0.f, 0.f, 0.f, 0.f);
            if (grow < M)
                v = *reinterpret_cast<const float4*>(X + (size_t)grow * K + k0 + cq * 4);
            if (RELU) {
                v.x = fmaxf(v.x, 0.f); v.y = fmaxf(v.y, 0.f);
                v.z = fmaxf(v.z, 0.f); v.w = fmaxf(v.w, 0.f);
            }
            As[cq * 4 + 0][r] = v.x;
            As[cq * 4 + 1][r] = v.y;
            As[cq * 4 + 2][r] = v.z;
            As[cq * 4 + 3][r] = v.w;
        }
        #pragma unroll
        for (int it = 0; it < 2; it++) {
            int s  = tid + it * 256;       // 16 rows x 32 quads
            int r  = s >> 5;
            int cq = s & 31;
            float4 v = *reinterpret_cast<const float4*>(W + (size_t)(k0 + r) * BN + cq * 4);
            *reinterpret_cast<float4*>(&Bs[r][cq * 4]) = v;
        }
        __syncthreads();

        #pragma unroll
        for (int k = 0; k < BK; k++) {
            float ra[TM];
            u64   rb2[TN / 2];
            *reinterpret_cast<float4*>(&ra[0]) = *reinterpret_cast<const float4*>(&As[k][trow]);
            *reinterpret_cast<float4*>(&ra[4]) = *reinterpret_cast<const float4*>(&As[k][trow + 4]);
            // Bs row is contiguous & 16B aligned: pairs land pre-packed in reg pairs
            const u64* bp = reinterpret_cast<const u64*>(&Bs[k][tcol]);
            rb2[0] = bp[0]; rb2[1] = bp[1]; rb2[2] = bp[2]; rb2[3] = bp[3];
            #pragma unroll
            for (int i = 0; i < TM; i++) {
                u64 ra2;
                DUP2(ra2, __float_as_uint(ra[i]));
                #pragma unroll
                for (int jp = 0; jp < TN / 2; jp++)
                    FMA2(acc2[i][jp], ra2, rb2[jp]);
            }
        }
        __syncthreads();
    }

    #pragma unroll
    for (int i = 0; i < TM; i++) {
        int grow = block_row + trow + i;
        if (grow >= M) break;
        float d = dis[grow];
        float o[TN];
        #pragma unroll
        for (int jp = 0; jp < TN / 2; jp++) {
            uint2 u = *reinterpret_cast<uint2*>(&acc2[i][jp]);
            o[2 * jp]     = __uint_as_float(u.x) * d;
            o[2 * jp + 1] = __uint_as_float(u.y) * d;
        }
        *reinterpret_cast<float4*>(H + (size_t)grow * D_HID + tcol)     = *reinterpret_cast<float4*>(&o[0]);
        *reinterpret_cast<float4*>(H + (size_t)grow * D_HID + tcol + 4) = *reinterpret_cast<float4*>(&o[4]);
    }
}

// ---------------------------------------------------------------------------
// Gather:  out[d] = dis[d]*( H'[d] + sum_{s in CSR[d]} H'[s] ) + bias
// One warp per node; lane l owns float4 at column 4l. 4-deep neighbor unroll.
// ---------------------------------------------------------------------------
__global__ __launch_bounds__(256)
void gather_kernel(const int* __restrict__ rowptr,
                   const int* __restrict__ col,
                   const float* __restrict__ dis,
                   const float* __restrict__ Hs,
                   const float* __restrict__ bias,
                   float* __restrict__ out, int n) {
    int w    = (blockIdx.x * blockDim.x + threadIdx.x) >> 5;
    int lane = threadIdx.x & 31;
    if (w >= n) return;

    const int beg = rowptr[w];
    const int end = rowptr[w + 1];
    const float* Hc = Hs + (size_t)lane * 4;

    float4 acc = *reinterpret_cast<const float4*>(Hc + (size_t)w * D_HID); // self

    int i = beg;
    for (; i + 4 <= end; i += 4) {
        int s0 = col[i], s1 = col[i + 1], s2 = col[i + 2], s3 = col[i + 3];
        float4 v0 = *reinterpret_cast<const float4*>(Hc + (size_t)s0 * D_HID);
        float4 v1 = *reinterpret_cast<const float4*>(Hc + (size_t)s1 * D_HID);
        float4 v2 = *reinterpret_cast<const float4*>(Hc + (size_t)s2 * D_HID);
        float4 v3 = *reinterpret_cast<const float4*>(Hc + (size_t)s3 * D_HID);
        acc.x += v0.x + v1.x + v2.x + v3.x;
        acc.y += v0.y + v1.y + v2.y + v3.y;
        acc.z += v0.z + v1.z + v2.z + v3.z;
        acc.w += v0.w + v1.w + v2.w + v3.w;
    }
    for (; i < end; i++) {
        int s = col[i];
        float4 v = *reinterpret_cast<const float4*>(Hc + (size_t)s * D_HID);
        acc.x += v.x; acc.y += v.y; acc.z += v.z; acc.w += v.w;
    }

    float dd  = dis[w];
    float4 bv = *reinterpret_cast<const float4*>(bias + (size_t)lane * 4);
    float4 o  = make_float4(fmaf(acc.x, dd, bv.x), fmaf(acc.y, dd, bv.y),
                            fmaf(acc.z, dd, bv.z), fmaf(acc.w, dd, bv.w));
    *reinterpret_cast<float4*>(out + (size_t)w * D_HID + (size_t)lane * 4) = o;
}

// ---------------------------------------------------------------------------
// Launch
// ---------------------------------------------------------------------------
static inline int cdiv(long long a, long long b) { return (int)((a + b - 1) / b); }

extern "C" void kernel_launch(void* const* d_in, const int* in_sizes, int n_in,
                              void* d_out, int out_size) {
    const float* X   = (const float*)d_in[0];   // [N, 256]
    const void*  EI  = d_in[1];                 // [2, E], int32 or int64
    const float* W1  = (const float*)d_in[2];   // [256, 128]
    const float* b1  = (const float*)d_in[3];   // [128]
    const float* W2  = (const float*)d_in[4];   // [128, 128]
    const float* b2  = (const float*)d_in[5];   // [128]
    float*       OUT = (float*)d_out;           // [N, 128]

    const int M  = in_sizes[0] / 256;    // 50000
    const int E  = in_sizes[1] / 2;      // 800000
    const int K1 = in_sizes[2] / D_HID;  // 256

    int *p_cnt, *p_rowptr, *p_cursor, *p_col;
    float *p_dis, *p_h, *p_agg, *p_h2;
    cudaGetSymbolAddress((void**)&p_cnt,    g_cnt);
    cudaGetSymbolAddress((void**)&p_rowptr, g_rowptr);
    cudaGetSymbolAddress((void**)&p_cursor, g_cursor);
    cudaGetSymbolAddress((void**)&p_col,    g_col);
    cudaGetSymbolAddress((void**)&p_dis,    g_dis);
    cudaGetSymbolAddress((void**)&p_h,      g_h);
    cudaGetSymbolAddress((void**)&p_agg,    g_agg);
    cudaGetSymbolAddress((void**)&p_h2,     g_h2);

    const int scan_blocks = cdiv(M, 256);   // 196 <= 256

    // --- edge dtype detection + CSR build ---
    detect_kernel  <<<1, 32>>>(EI, E);
    zero_cnt_kernel<<<cdiv(M, 256), 256>>>(p_cnt, M);
    hist_kernel    <<<cdiv(E, 256), 256>>>(EI, p_cnt, E);
    scanA_kernel   <<<scan_blocks, 256>>>(p_cnt, M);
    scanB_kernel   <<<1, 256>>>(scan_blocks);
    scanC_kernel   <<<scan_blocks, 256>>>(p_cnt, p_rowptr, p_cursor, p_dis, M);
    fill_kernel    <<<cdiv(E, 256), 256>>>(EI, p_cursor, p_col, E);

    const int gemm_blocks   = cdiv(M, BM);
    const int gather_blocks = cdiv(M, 8);   // 8 warps per 256-thread block

    // --- layer 1 ---
    gemm_scaled_kernel<false><<<gemm_blocks, 256>>>(X, W1, p_dis, p_h, M, K1);
    gather_kernel<<<gather_blocks, 256>>>(p_rowptr, p_col, p_dis, p_h, b1, p_agg, M);

    // --- layer 2 ---
    gemm_scaled_kernel<true><<<gemm_blocks, 256>>>(p_agg, W2, p_dis, p_h2, M, D_HID);
    gather_kernel<<<gather_blocks, 256>>>(p_rowptr, p_col, p_dis, p_h2, b2, OUT, M);
}